// round 2
// baseline (speedup 1.0000x reference)
#include <cuda_runtime.h>
#include <cuda_bf16.h>

#define MSGD 128
#define KNB 32
#define NB 8
#define GROUPS 2
#define NODES_PER_CTA (NB * GROUPS)
#define THREADS 256
#define XS 136  // padded neighbor-row stride (floats) -> conflict-free column access

// Precomputed operator scratch (allocation-free: __device__ globals)
__device__ __align__(16) float g_A[MSGD * MSGD];    // g_A[e*128+d] = A[d][e] = sum_a Wk[a][d]*Wq[a][e]
__device__ __align__(16) float g_WvT[MSGD * MSGD];  // g_WvT[d*128+m] = Wv[m][d]
__device__ __align__(16) float g_u[MSGD];           // u[d] = sum_a Wk[a][d]*bq[a]

// ---------------------------------------------------------------------------
// Prep: A = Wk^T Wq (stored transposed), u = Wk^T bq, WvT = Wv^T
// ---------------------------------------------------------------------------
__global__ void prep_kernel(const float* __restrict__ Wq, const float* __restrict__ bq,
                            const float* __restrict__ Wk, const float* __restrict__ Wv) {
    const int b = blockIdx.x;   // e (for A), d (for WvT)
    const int t = threadIdx.x;  // d (for A), m (for WvT)
    float acc = 0.f;
#pragma unroll 8
    for (int a = 0; a < MSGD; ++a)
        acc = fmaf(Wk[a * MSGD + t], Wq[a * MSGD + b], acc);
    g_A[b * MSGD + t] = acc;
    g_WvT[b * MSGD + t] = Wv[t * MSGD + b];
    if (b == 0) {
        float u = 0.f;
#pragma unroll 8
        for (int a = 0; a < MSGD; ++a)
            u = fmaf(Wk[a * MSGD + t], bq[a], u);
        g_u[t] = u;
    }
}

// ---------------------------------------------------------------------------
// cp.async helpers
// ---------------------------------------------------------------------------
__device__ __forceinline__ void cp16(float* dst, const float* src) {
    unsigned s = (unsigned)__cvta_generic_to_shared(dst);
    asm volatile("cp.async.ca.shared.global [%0], [%1], 16;\n" ::"r"(s), "l"(src));
}
#define CP_COMMIT() asm volatile("cp.async.commit_group;\n" ::: "memory")
#define CP_WAIT(n)  asm volatile("cp.async.wait_group %0;\n" ::"n"(n) : "memory")

// Load one node's 32x128 neighbor tile into a padded smem buffer (async).
__device__ __forceinline__ void load_x(float* xbuf, const float* __restrict__ nmsg,
                                       int node, int N) {
    if (node >= N) node = N - 1;
    const float* src = nmsg + (size_t)node * (KNB * MSGD);
    const int t = threadIdx.x;
#pragma unroll
    for (int it = 0; it < 4; ++it) {
        int idx = t + it * THREADS;  // float4 index, 0..1023
        int row = idx >> 5;          // /32 float4s per row
        int c4  = idx & 31;
        cp16(xbuf + row * XS + c4 * 4, src + (size_t)idx * 4);
    }
}

// ---------------------------------------------------------------------------
// Main fused kernel: per CTA = 16 nodes (2 groups of 8)
// ---------------------------------------------------------------------------
__global__ __launch_bounds__(THREADS, 1)
void gac_kernel(const float* __restrict__ qmsg, const float* __restrict__ nmsg,
                const float* __restrict__ bv, float* __restrict__ outp, int N) {
    extern __shared__ float sm[];
    float* sA   = sm;           // 16384
    float* sWvT = sm + 16384;   // 16384
    float* sX   = sm + 32768;   // 2 * 32 * 136 = 8704
    float* sQ   = sm + 41472;   // 8*128
    float* sQe  = sm + 42496;   // 8*128
    float* sY   = sm + 43520;   // 8*128
    float* sO   = sm + 44544;   // 8*128
    float* sU   = sm + 45568;   // 128
    float* sBv  = sm + 45696;   // 128
    float* sSc  = sm + 45824;   // 32
    float* sAtt = sm + 45856;   // 32

    const int t = threadIdx.x;
    const int w = t >> 5;
    const int l = t & 31;

    // Cache operator matrices in smem (once per CTA)
    for (int idx = t; idx < 4096; idx += THREADS) {
        reinterpret_cast<float4*>(sA)[idx]   = reinterpret_cast<const float4*>(g_A)[idx];
        reinterpret_cast<float4*>(sWvT)[idx] = reinterpret_cast<const float4*>(g_WvT)[idx];
    }
    if (t < MSGD) { sU[t] = g_u[t]; sBv[t] = bv[t]; }

    const int ctaBase = blockIdx.x * NODES_PER_CTA;

    // GEMM-phase thread mapping: warp w owns 16 output columns, lane halves own 4 nodes each
    const int dcol  = w * 16 + (l & 15);
    const int ibase = (l >> 4) * 4;

    for (int g = 0; g < GROUPS; ++g) {
        const int nodeBase = ctaBase + g * NB;

        // Stage the 8 query rows
        {
            int node = t >> 5;
            int gn = nodeBase + node;
            if (gn >= N) gn = N - 1;
            float4 v = *reinterpret_cast<const float4*>(qmsg + (size_t)gn * MSGD + l * 4);
            *reinterpret_cast<float4*>(sQ + node * MSGD + l * 4) = v;
        }
        if (g == 0) {  // prefetch node 0 neighbors
            load_x(sX, nmsg, nodeBase, N);
            CP_COMMIT();
        }
        __syncthreads();

        // Phase A: Qeff[i][d] = sum_e A[d][e] * q_i[e] + u[d]   (8-node batched matvec)
        {
            const float u = sU[dcol];
            float acc0 = u, acc1 = u, acc2 = u, acc3 = u;
            const float* Ac = sA + dcol;
            const float* q0 = sQ + (ibase + 0) * MSGD;
            const float* q1 = sQ + (ibase + 1) * MSGD;
            const float* q2 = sQ + (ibase + 2) * MSGD;
            const float* q3 = sQ + (ibase + 3) * MSGD;
#pragma unroll 4
            for (int e = 0; e < MSGD; e += 4) {
                float a0 = Ac[(e + 0) * MSGD], a1 = Ac[(e + 1) * MSGD];
                float a2 = Ac[(e + 2) * MSGD], a3 = Ac[(e + 3) * MSGD];
                float4 v0 = *reinterpret_cast<const float4*>(q0 + e);
                float4 v1 = *reinterpret_cast<const float4*>(q1 + e);
                float4 v2 = *reinterpret_cast<const float4*>(q2 + e);
                float4 v3 = *reinterpret_cast<const float4*>(q3 + e);
                acc0 = fmaf(a0, v0.x, acc0); acc0 = fmaf(a1, v0.y, acc0);
                acc0 = fmaf(a2, v0.z, acc0); acc0 = fmaf(a3, v0.w, acc0);
                acc1 = fmaf(a0, v1.x, acc1); acc1 = fmaf(a1, v1.y, acc1);
                acc1 = fmaf(a2, v1.z, acc1); acc1 = fmaf(a3, v1.w, acc1);
                acc2 = fmaf(a0, v2.x, acc2); acc2 = fmaf(a1, v2.y, acc2);
                acc2 = fmaf(a2, v2.z, acc2); acc2 = fmaf(a3, v2.w, acc2);
                acc3 = fmaf(a0, v3.x, acc3); acc3 = fmaf(a1, v3.y, acc3);
                acc3 = fmaf(a2, v3.z, acc3); acc3 = fmaf(a3, v3.w, acc3);
            }
            sQe[(ibase + 0) * MSGD + dcol] = acc0;
            sQe[(ibase + 1) * MSGD + dcol] = acc1;
            sQe[(ibase + 2) * MSGD + dcol] = acc2;
            sQe[(ibase + 3) * MSGD + dcol] = acc3;
        }
        __syncthreads();

        // Per-node: scores -> softmax -> y = sum att_k * x_k   (double-buffered x)
        for (int i = 0; i < NB; ++i) {
            bool pref = false; int nn = 0;
            if (i + 1 < NB)            { nn = nodeBase + i + 1;      pref = true; }
            else if (g + 1 < GROUPS)   { nn = ctaBase + (g + 1) * NB; pref = true; }
            if (pref) {
                load_x(sX + ((i + 1) & 1) * KNB * XS, nmsg, nn, N);
                CP_COMMIT();
                CP_WAIT(1);
            } else {
                CP_WAIT(0);
            }
            __syncthreads();

            const float* xb = sX + (i & 1) * KNB * XS;

            // scores_k = Qeff_i . x_k  : warp w -> k in [4w,4w+4), 8 lanes per k
            {
                const int k  = w * 4 + (l >> 3);
                const int l8 = l & 7;
                const float* xr = xb + k * XS;
                const float* Qe = sQe + i * MSGD;
                float acc = 0.f;
#pragma unroll
                for (int j = 0; j < 16; ++j) {
                    int d = l8 + j * 8;
                    acc = fmaf(Qe[d], xr[d], acc);
                }
                acc += __shfl_xor_sync(0xffffffffu, acc, 1);
                acc += __shfl_xor_sync(0xffffffffu, acc, 2);
                acc += __shfl_xor_sync(0xffffffffu, acc, 4);
                if (l8 == 0) sSc[k] = acc;
            }
            __syncthreads();

            if (t < 32) {  // softmax over 32 neighbors (warp 0)
                float s = sSc[t] * 0.0883883476483184f;  // 1/sqrt(128)
                float m = s;
#pragma unroll
                for (int o = 16; o > 0; o >>= 1)
                    m = fmaxf(m, __shfl_xor_sync(0xffffffffu, m, o));
                float p = __expf(s - m);
                float sum = p;
#pragma unroll
                for (int o = 16; o > 0; o >>= 1)
                    sum += __shfl_xor_sync(0xffffffffu, sum, o);
                sAtt[t] = p / sum;
            }
            __syncthreads();

            if (t < MSGD) {  // y_i[d] = sum_k att_k * x_k[d]
                float acc = 0.f;
#pragma unroll 8
                for (int k = 0; k < KNB; ++k)
                    acc = fmaf(sAtt[k], xb[k * XS + t], acc);
                sY[i * MSGD + t] = acc;
            }
            __syncthreads();
        }

        // Phase C: out[i][m] = sum_d Wv[m][d] * y_i[d] + bv[m]
        {
            float acc0 = 0.f, acc1 = 0.f, acc2 = 0.f, acc3 = 0.f;
            const float* Wc = sWvT + dcol;
            const float* y0 = sY + (ibase + 0) * MSGD;
            const float* y1 = sY + (ibase + 1) * MSGD;
            const float* y2 = sY + (ibase + 2) * MSGD;
            const float* y3 = sY + (ibase + 3) * MSGD;
#pragma unroll 4
            for (int e = 0; e < MSGD; e += 4) {
                float a0 = Wc[(e + 0) * MSGD], a1 = Wc[(e + 1) * MSGD];
                float a2 = Wc[(e + 2) * MSGD], a3 = Wc[(e + 3) * MSGD];
                float4 v0 = *reinterpret_cast<const float4*>(y0 + e);
                float4 v1 = *reinterpret_cast<const float4*>(y1 + e);
                float4 v2 = *reinterpret_cast<const float4*>(y2 + e);
                float4 v3 = *reinterpret_cast<const float4*>(y3 + e);
                acc0 = fmaf(a0, v0.x, acc0); acc0 = fmaf(a1, v0.y, acc0);
                acc0 = fmaf(a2, v0.z, acc0); acc0 = fmaf(a3, v0.w, acc0);
                acc1 = fmaf(a0, v1.x, acc1); acc1 = fmaf(a1, v1.y, acc1);
                acc1 = fmaf(a2, v1.z, acc1); acc1 = fmaf(a3, v1.w, acc1);
                acc2 = fmaf(a0, v2.x, acc2); acc2 = fmaf(a1, v2.y, acc2);
                acc2 = fmaf(a2, v2.z, acc2); acc2 = fmaf(a3, v2.w, acc2);
                acc3 = fmaf(a0, v3.x, acc3); acc3 = fmaf(a1, v3.y, acc3);
                acc3 = fmaf(a2, v3.z, acc3); acc3 = fmaf(a3, v3.w, acc3);
            }
            const float b = sBv[dcol];
            sO[(ibase + 0) * MSGD + dcol] = acc0 + b;
            sO[(ibase + 1) * MSGD + dcol] = acc1 + b;
            sO[(ibase + 2) * MSGD + dcol] = acc2 + b;
            sO[(ibase + 3) * MSGD + dcol] = acc3 + b;
        }
        __syncthreads();

        // Coalesced output write
        {
            int node = t >> 5;
            int gn = nodeBase + node;
            if (gn < N) {
                float4 v = *reinterpret_cast<const float4*>(sO + node * MSGD + l * 4);
                *reinterpret_cast<float4*>(outp + (size_t)gn * MSGD + l * 4) = v;
            }
        }
        __syncthreads();
    }
}

// ---------------------------------------------------------------------------
// Harness entry
// ---------------------------------------------------------------------------
extern "C" void kernel_launch(void* const* d_in, const int* in_sizes, int n_in,
                              void* d_out, int out_size) {
    const float* qmsg = (const float*)d_in[0];  // [N,128]
    const float* nmsg = (const float*)d_in[1];  // [N,32,128]
    const float* Wq   = (const float*)d_in[2];  // [128,128]
    const float* bq   = (const float*)d_in[3];  // [128]
    const float* Wk   = (const float*)d_in[4];  // [128,128]
    // d_in[5] = bk: mathematically irrelevant (softmax-invariant constant)
    const float* Wv   = (const float*)d_in[6];  // [128,128]
    const float* bv   = (const float*)d_in[7];  // [128]
    float* out = (float*)d_out;

    const int N = in_sizes[0] / MSGD;

    prep_kernel<<<MSGD, MSGD>>>(Wq, bq, Wk, Wv);

    const int smemBytes = 45888 * (int)sizeof(float);  // ~183.6 KB
    cudaFuncSetAttribute(gac_kernel, cudaFuncAttributeMaxDynamicSharedMemorySize, smemBytes);

    const int grid = (N + NODES_PER_CTA - 1) / NODES_PER_CTA;
    gac_kernel<<<grid, THREADS, smemBytes>>>(qmsg, nmsg, bv, out, N);
}

// round 3
// speedup vs baseline: 1.3496x; 1.3496x over previous
#include <cuda_runtime.h>

#define MSGD 128
#define KNB 32
#define XS 132                 // padded row stride (floats); 528B rows, 16B aligned
#define TILE_F (KNB * XS)      // 4224 floats per warp tile
#define NWARP 8
#define THREADS 256

typedef unsigned long long ull;

// Precomputed operators (allocation-free __device__ scratch)
// g_A4[(e>>2)*128 + d]*4 + (e&3)] = A[d][e],  A = Wk^T Wq  (Qeff = A q + u)
// g_W4[(e>>2)*128 + m]*4 + (e&3)] = Wv[m][e]               (out  = Wv y + bv)
__device__ __align__(16) float g_A4[MSGD * MSGD];
__device__ __align__(16) float g_W4[MSGD * MSGD];
__device__ __align__(16) float g_u[MSGD];   // u = Wk^T bq

// ---------------------------------------------------------------------------
// packed fp32x2 helpers
// ---------------------------------------------------------------------------
__device__ __forceinline__ ull pack2(float x, float y) {
    ull r; asm("mov.b64 %0,{%1,%2};" : "=l"(r) : "f"(x), "f"(y)); return r;
}
__device__ __forceinline__ void fma2(ull& d, ull a, ull b) {
    asm("fma.rn.f32x2 %0,%1,%2,%0;" : "+l"(d) : "l"(a), "l"(b));
}
__device__ __forceinline__ float sum2(ull v) {
    float x, y; asm("mov.b64 {%0,%1},%2;" : "=f"(x), "=f"(y) : "l"(v)); return x + y;
}

// ---------------------------------------------------------------------------
// Prep: A = Wk^T Wq, u = Wk^T bq, Wv repacked; e-pair-friendly float4 layout
// ---------------------------------------------------------------------------
__global__ void prep_kernel(const float* __restrict__ Wq, const float* __restrict__ bq,
                            const float* __restrict__ Wk, const float* __restrict__ Wv) {
    const int e = blockIdx.x;
    const int d = threadIdx.x;
    float acc = 0.f;
#pragma unroll 8
    for (int a = 0; a < MSGD; ++a)
        acc = fmaf(Wk[a * MSGD + d], Wq[a * MSGD + e], acc);
    g_A4[((e >> 2) * MSGD + d) * 4 + (e & 3)] = acc;
    g_W4[((e >> 2) * MSGD + d) * 4 + (e & 3)] = Wv[d * MSGD + e];
    if (e == 0) {
        float u = 0.f;
#pragma unroll 8
        for (int a = 0; a < MSGD; ++a)
            u = fmaf(Wk[a * MSGD + d], bq[a], u);
        g_u[d] = u;
    }
}

// ---------------------------------------------------------------------------
// cp.async helpers
// ---------------------------------------------------------------------------
__device__ __forceinline__ void cp16(float* dst, const float* src) {
    unsigned s = (unsigned)__cvta_generic_to_shared(dst);
    asm volatile("cp.async.cg.shared.global [%0], [%1], 16;\n" ::"r"(s), "l"(src));
}
#define CP_COMMIT() asm volatile("cp.async.commit_group;\n" ::: "memory")
#define CP_WAIT0()  asm volatile("cp.async.wait_group 0;\n" ::: "memory")

// ---------------------------------------------------------------------------
// Main kernel: 8 nodes per group, warp-per-node attention, batched GEMM phases
// ---------------------------------------------------------------------------
__global__ __launch_bounds__(THREADS, 1)
void gac_kernel(const float* __restrict__ qmsg, const float* __restrict__ nmsg,
                const float* __restrict__ bv, float* __restrict__ outp,
                int N, int G) {
    extern __shared__ float sm[];
    float* sX  = sm;                       // 8 * 4224 = 33792 floats (warp-private tiles)
    float* sQe = sm + NWARP * TILE_F;      // 8 * 128
    float* sY  = sQe + NWARP * MSGD;       // 8 * 128
    float* sSc = sY + NWARP * MSGD;        // 8 * 32

    const int t = threadIdx.x;
    const int w = t >> 5;
    const int l = t & 31;
    const int qbase = (w >> 2) * 4;        // node quad for GEMM phases (0 or 4)
    const int dcol  = (w & 3) * 32 + l;    // output column 0..127, coalesced per warp

    const ulonglong2* gA = reinterpret_cast<const ulonglong2*>(g_A4);
    const ulonglong2* gW = reinterpret_cast<const ulonglong2*>(g_W4);
    const float uu = g_u[dcol];
    const float bb = bv[dcol];

    float* xb = sX + w * TILE_F;           // this warp's tile
    const int ctaBase = blockIdx.x * (8 * G);

    // ---- issue cp.async for this warp's tile of group with base 'nb' ----
    auto cp_issue = [&](int nb) {
        int gn = nb + w; if (gn >= N) gn = N - 1;
        const float* src = nmsg + (size_t)gn * (KNB * MSGD);
#pragma unroll
        for (int j = 0; j < KNB; ++j)
            cp16(xb + j * XS + l * 4, src + (size_t)(j * 32 + l) * 4);
        CP_COMMIT();
    };

    // ---- phase A: Qeff[i][dcol] = sum_e A[dcol][e] q_i[e] + u  (4 nodes) ----
    auto phaseA = [&](int nb) {
        int n0 = nb + qbase + 0; if (n0 >= N) n0 = N - 1;
        int n1 = nb + qbase + 1; if (n1 >= N) n1 = N - 1;
        int n2 = nb + qbase + 2; if (n2 >= N) n2 = N - 1;
        int n3 = nb + qbase + 3; if (n3 >= N) n3 = N - 1;
        const ulonglong2* q0 = reinterpret_cast<const ulonglong2*>(qmsg + (size_t)n0 * MSGD);
        const ulonglong2* q1 = reinterpret_cast<const ulonglong2*>(qmsg + (size_t)n1 * MSGD);
        const ulonglong2* q2 = reinterpret_cast<const ulonglong2*>(qmsg + (size_t)n2 * MSGD);
        const ulonglong2* q3 = reinterpret_cast<const ulonglong2*>(qmsg + (size_t)n3 * MSGD);
        ull a0 = 0, a1 = 0, a2 = 0, a3 = 0;
#pragma unroll 8
        for (int e4 = 0; e4 < 32; ++e4) {
            ulonglong2 av = gA[e4 * MSGD + dcol];   // coalesced, L1/L2-resident
            ulonglong2 p0 = q0[e4];                  // broadcast (same addr all lanes)
            ulonglong2 p1 = q1[e4];
            ulonglong2 p2 = q2[e4];
            ulonglong2 p3 = q3[e4];
            fma2(a0, av.x, p0.x); fma2(a0, av.y, p0.y);
            fma2(a1, av.x, p1.x); fma2(a1, av.y, p1.y);
            fma2(a2, av.x, p2.x); fma2(a2, av.y, p2.y);
            fma2(a3, av.x, p3.x); fma2(a3, av.y, p3.y);
        }
        sQe[(qbase + 0) * MSGD + dcol] = sum2(a0) + uu;
        sQe[(qbase + 1) * MSGD + dcol] = sum2(a1) + uu;
        sQe[(qbase + 2) * MSGD + dcol] = sum2(a2) + uu;
        sQe[(qbase + 3) * MSGD + dcol] = sum2(a3) + uu;
    };

    // ---- phase C: out[i][dcol] = sum_e Wv[dcol][e] y_i[e] + bv  (4 nodes) ----
    auto phaseC = [&](int nb) {
        const ulonglong2* y0 = reinterpret_cast<const ulonglong2*>(sY + (qbase + 0) * MSGD);
        const ulonglong2* y1 = reinterpret_cast<const ulonglong2*>(sY + (qbase + 1) * MSGD);
        const ulonglong2* y2 = reinterpret_cast<const ulonglong2*>(sY + (qbase + 2) * MSGD);
        const ulonglong2* y3 = reinterpret_cast<const ulonglong2*>(sY + (qbase + 3) * MSGD);
        ull a0 = 0, a1 = 0, a2 = 0, a3 = 0;
#pragma unroll 8
        for (int e4 = 0; e4 < 32; ++e4) {
            ulonglong2 av = gW[e4 * MSGD + dcol];
            ulonglong2 p0 = y0[e4];                  // smem broadcast
            ulonglong2 p1 = y1[e4];
            ulonglong2 p2 = y2[e4];
            ulonglong2 p3 = y3[e4];
            fma2(a0, av.x, p0.x); fma2(a0, av.y, p0.y);
            fma2(a1, av.x, p1.x); fma2(a1, av.y, p1.y);
            fma2(a2, av.x, p2.x); fma2(a2, av.y, p2.y);
            fma2(a3, av.x, p3.x); fma2(a3, av.y, p3.y);
        }
        int n0 = nb + qbase;
        if (n0 + 0 < N) outp[(size_t)(n0 + 0) * MSGD + dcol] = sum2(a0) + bb;
        if (n0 + 1 < N) outp[(size_t)(n0 + 1) * MSGD + dcol] = sum2(a1) + bb;
        if (n0 + 2 < N) outp[(size_t)(n0 + 2) * MSGD + dcol] = sum2(a2) + bb;
        if (n0 + 3 < N) outp[(size_t)(n0 + 3) * MSGD + dcol] = sum2(a3) + bb;
    };

    // ---- prologue: first tile loads + first Qeff ----
    cp_issue(ctaBase);
    phaseA(ctaBase);

    for (int g = 0; g < G; ++g) {
        const int nodeBase = ctaBase + g * 8;

        __syncthreads();            // sQe(g) visible to all warps
        CP_WAIT0();                 // this warp's tile ready (warp-private)

        // ---- attention for node (nodeBase + w), entirely in-warp ----
        {
            const float* Qe = sQe + w * MSGD;
            const int l8 = l & 7;
            const int kq = l >> 3;
            // hoist Qeff sub-vector (16 dims this lane owns) into regs
            ulonglong2 qp0 = *reinterpret_cast<const ulonglong2*>(Qe + 4 * l8);
            ulonglong2 qp1 = *reinterpret_cast<const ulonglong2*>(Qe + 4 * l8 + 32);
            ulonglong2 qp2 = *reinterpret_cast<const ulonglong2*>(Qe + 4 * l8 + 64);
            ulonglong2 qp3 = *reinterpret_cast<const ulonglong2*>(Qe + 4 * l8 + 96);
            // scores: 8 lanes per neighbor, 4 neighbors per iteration
#pragma unroll
            for (int m = 0; m < 8; ++m) {
                const float* xr = xb + (4 * m + kq) * XS;
                ulonglong2 x0 = *reinterpret_cast<const ulonglong2*>(xr + 4 * l8);
                ulonglong2 x1 = *reinterpret_cast<const ulonglong2*>(xr + 4 * l8 + 32);
                ulonglong2 x2 = *reinterpret_cast<const ulonglong2*>(xr + 4 * l8 + 64);
                ulonglong2 x3 = *reinterpret_cast<const ulonglong2*>(xr + 4 * l8 + 96);
                ull accA = 0, accB = 0;
                fma2(accA, x0.x, qp0.x); fma2(accB, x0.y, qp0.y);
                fma2(accA, x1.x, qp1.x); fma2(accB, x1.y, qp1.y);
                fma2(accA, x2.x, qp2.x); fma2(accB, x2.y, qp2.y);
                fma2(accA, x3.x, qp3.x); fma2(accB, x3.y, qp3.y);
                float r = sum2(accA) + sum2(accB);
                r += __shfl_xor_sync(0xffffffffu, r, 1);
                r += __shfl_xor_sync(0xffffffffu, r, 2);
                r += __shfl_xor_sync(0xffffffffu, r, 4);
                if (l8 == 0) sSc[w * 32 + 4 * m + kq] = r;
            }
            __syncwarp();

            // softmax over the 32 neighbors (lane l = neighbor l)
            float s = sSc[w * 32 + l] * 0.08838834764831843f;  // 1/sqrt(128)
            float mx = s;
#pragma unroll
            for (int o = 16; o > 0; o >>= 1)
                mx = fmaxf(mx, __shfl_xor_sync(0xffffffffu, mx, o));
            float p = __expf(s - mx);
            float sum = p;
#pragma unroll
            for (int o = 16; o > 0; o >>= 1)
                sum += __shfl_xor_sync(0xffffffffu, sum, o);
            const float att = p / sum;

            // y[d] = sum_k att_k x_k[d] ; lane owns d = 4l..4l+3
            ull ya = 0, yb = 0;
#pragma unroll
            for (int k = 0; k < KNB; ++k) {
                float a = __shfl_sync(0xffffffffu, att, k);
                ull a2 = pack2(a, a);
                ulonglong2 xv = *reinterpret_cast<const ulonglong2*>(xb + k * XS + 4 * l);
                fma2(ya, a2, xv.x);
                fma2(yb, a2, xv.y);
            }
            ulonglong2 yy; yy.x = ya; yy.y = yb;
            *reinterpret_cast<ulonglong2*>(sY + w * MSGD + 4 * l) = yy;
        }

        __syncwarp();
        if (g + 1 < G) cp_issue(nodeBase + 8);   // prefetch own next tile (warp-private)

        __syncthreads();            // sY(g) visible to all warps

        if (g + 1 < G) phaseA(nodeBase + 8);     // overlaps in-flight cp.async
        phaseC(nodeBase);
    }
}

// ---------------------------------------------------------------------------
// Harness entry
// ---------------------------------------------------------------------------
extern "C" void kernel_launch(void* const* d_in, const int* in_sizes, int n_in,
                              void* d_out, int out_size) {
    const float* qmsg = (const float*)d_in[0];  // [N,128]
    const float* nmsg = (const float*)d_in[1];  // [N,32,128]
    const float* Wq   = (const float*)d_in[2];  // [128,128]
    const float* bq   = (const float*)d_in[3];  // [128]
    const float* Wk   = (const float*)d_in[4];  // [128,128]
    // d_in[5] = bk: softmax-invariant constant, mathematically irrelevant
    const float* Wv   = (const float*)d_in[6];  // [128,128]
    const float* bv   = (const float*)d_in[7];  // [128]
    float* out = (float*)d_out;

    const int N = in_sizes[0] / MSGD;

    prep_kernel<<<MSGD, MSGD>>>(Wq, bq, Wk, Wv);

    // one-wave grid: ~148 CTAs, G groups of 8 nodes each
    const int target = 148;
    int G = (N + 8 * target - 1) / (8 * target);
    if (G < 1) G = 1;
    int grid = (N + 8 * G - 1) / (8 * G);

    const int smemBytes = (NWARP * TILE_F + 2 * NWARP * MSGD + NWARP * 32) * (int)sizeof(float);
    cudaFuncSetAttribute(gac_kernel, cudaFuncAttributeMaxDynamicSharedMemorySize, smemBytes);

    gac_kernel<<<grid, THREADS, smemBytes>>>(qmsg, nmsg, bv, out, N, G);
}